// round 9
// baseline (speedup 1.0000x reference)
#include <cuda_runtime.h>

#define FULL 0xffffffffu

// Scratch (static device globals — allocation-free).
__device__ float g_partial[4][64][4096];   // per-(head-group,b,l) partials (4 MB)
__device__ float g_S[3][64][128];          // per-quarter dot partials S_q[b][i]

__device__ __forceinline__ float tanh_approx(float v) {
    float r;
    asm("tanh.approx.f32 %0, %1;" : "=f"(r) : "f"(v));
    return r;
}

// ---------------------------------------------------------------------------
// K0: quarter partial dots  S_q[b][i] = sum_{j in quarter q} W1[i,j]*x[b,j]
// grid (16 batch-quads, 8 head-chunks of 16, 3 quarters) = 384 blocks, 256 thr.
// Register-light: warp = 2 heads x 4 batches (acc = 8 regs), x staged in smem.
// ~40 regs -> 3+ blocks/SM resident, latency hidden.
// ---------------------------------------------------------------------------
__global__ __launch_bounds__(256)
void nade_carry_kernel(const float* __restrict__ x,
                       const float* __restrict__ W1)
{
    __shared__ float xs[4 * 1024];             // 16 KB: 4 batch quarter-rows

    const int bq   = blockIdx.x;               // batch quad
    const int hg   = blockIdx.y;               // head chunk (16 heads)
    const int q    = blockIdx.z;               // quarter 0..2
    const int tid  = threadIdx.x;
    const int w    = tid >> 5;                 // 8 warps
    const int lane = tid & 31;

    const float4* x4  = reinterpret_cast<const float4*>(x);
    float4*       xs4 = reinterpret_cast<float4*>(xs);
    for (int idx = tid; idx < 1024; idx += 256) {
        const int nb = idx >> 8;
        const int r  = idx & 255;
        xs4[idx] = x4[(bq * 4 + nb) * 1024 + q * 256 + r];
    }
    __syncthreads();

    const float4* W1_4 = reinterpret_cast<const float4*>(W1);
    const int i0 = hg * 16 + w * 2;            // warp's 2 heads

    float accA[4], accB[4];
    #pragma unroll
    for (int nb = 0; nb < 4; nb++) { accA[nb] = 0.f; accB[nb] = 0.f; }

    #pragma unroll
    for (int c = 0; c < 8; c++) {
        const int j4 = c * 32 + lane;          // float4 idx within quarter
        const float4 wA = W1_4[(i0 + 0) * 1024 + q * 256 + j4];
        const float4 wB = W1_4[(i0 + 1) * 1024 + q * 256 + j4];
        #pragma unroll
        for (int nb = 0; nb < 4; nb++) {
            const float4 xv = xs4[nb * 256 + j4];
            accA[nb] = fmaf(xv.x, wA.x, fmaf(xv.y, wA.y,
                       fmaf(xv.z, wA.z, fmaf(xv.w, wA.w, accA[nb]))));
            accB[nb] = fmaf(xv.x, wB.x, fmaf(xv.y, wB.y,
                       fmaf(xv.z, wB.z, fmaf(xv.w, wB.w, accB[nb]))));
        }
    }

    // Butterfly reduce the 8 accumulators (level-batched for overlap).
    #pragma unroll
    for (int o = 16; o > 0; o >>= 1) {
        #pragma unroll
        for (int nb = 0; nb < 4; nb++) {
            accA[nb] += __shfl_down_sync(FULL, accA[nb], o);
            accB[nb] += __shfl_down_sync(FULL, accB[nb], o);
        }
    }
    if (lane == 0) {
        #pragma unroll
        for (int nb = 0; nb < 4; nb++) {
            g_S[q][bq * 4 + nb][i0 + 0] = accA[nb];
            g_S[q][bq * 4 + nb][i0 + 1] = accB[nb];
        }
    }
}

// ---------------------------------------------------------------------------
// K1: scan + sigmoid + head reduction. 4 batches/block, 32 heads/block,
// quarter of j. grid (16 bq, 4 head-groups, 4 quarters) = 256 blocks, 256 thr,
// 2 blocks/SM. Lane owns 8 consecutive j -> tile = 256 j, 4 tiles/quarter:
// HALVES the number of 5-level warp scans per element vs 4-j lanes.
// ---------------------------------------------------------------------------
__global__ __launch_bounds__(256, 2)
void nade_main_kernel(const float* __restrict__ x,
                      const float* __restrict__ W1,
                      const float* __restrict__ b1,
                      const float* __restrict__ W2)
{
    __shared__ float xs[4 * 1024];             // 16 KB: 4 batch quarter-rows
    __shared__ float red[8][4][256];           // 32 KB: warp partials

    const int b0   = blockIdx.x * 4;
    const int g    = blockIdx.y;               // head group of 32
    const int q    = blockIdx.z;
    const int tid  = threadIdx.x;
    const int w    = tid >> 5;                 // 8 warps, warp = 4 heads
    const int lane = tid & 31;

    const float4* x4  = reinterpret_cast<const float4*>(x);
    float4*       xs4 = reinterpret_cast<float4*>(xs);
    for (int idx = tid; idx < 1024; idx += 256) {
        const int nb = idx >> 8;
        const int r  = idx & 255;
        xs4[idx] = x4[(b0 + nb) * 1024 + q * 256 + r];
    }
    __syncthreads();

    const int i0 = g * 32 + w * 4;

    // cb[h][nb] = 0.5 * (b1[i] + carry from previous quarters + running prefix)
    float cb[16];
    #pragma unroll
    for (int h = 0; h < 4; h++) {
        const float base = b1[i0 + h];
        #pragma unroll
        for (int nb = 0; nb < 4; nb++) {
            float c = base;
            for (int qq = 0; qq < q; qq++) c += g_S[qq][b0 + nb][i0 + h];
            cb[h * 4 + nb] = 0.5f * c;
        }
    }

    const float4* W1_4 = reinterpret_cast<const float4*>(W1);
    const float4* W2_4 = reinterpret_cast<const float4*>(W2);

    for (int t = 0; t < 4; ++t) {
        const int jv = t * 64 + lane * 2;      // first of 2 float4s (8 j) per lane

        // x values for the 4 batches (8 floats each), reused across 4 heads.
        float4 xa[4], xb[4];
        #pragma unroll
        for (int nb = 0; nb < 4; nb++) {
            xa[nb] = xs4[nb * 256 + jv];
            xb[nb] = xs4[nb * 256 + jv + 1];
        }

        float acc[4][8];
        #pragma unroll
        for (int nb = 0; nb < 4; nb++)
            #pragma unroll
            for (int m = 0; m < 8; m++) acc[nb][m] = 0.f;

        #pragma unroll
        for (int h = 0; h < 4; h++) {
            const int i = i0 + h;
            const float4 w1a = W1_4[i * 1024 + q * 256 + jv];
            const float4 w1b = W1_4[i * 1024 + q * 256 + jv + 1];
            const float4 w2a = W2_4[i * 1024 + q * 256 + jv];
            const float4 w2b = W2_4[i * 1024 + q * 256 + jv + 1];

            // In-lane inclusive prefix of 8 products, all 4 batches.
            float s[4][8], inc[4];
            #pragma unroll
            for (int nb = 0; nb < 4; nb++) {
                s[nb][0] = xa[nb].x * w1a.x;
                s[nb][1] = fmaf(xa[nb].y, w1a.y, s[nb][0]);
                s[nb][2] = fmaf(xa[nb].z, w1a.z, s[nb][1]);
                s[nb][3] = fmaf(xa[nb].w, w1a.w, s[nb][2]);
                s[nb][4] = fmaf(xb[nb].x, w1b.x, s[nb][3]);
                s[nb][5] = fmaf(xb[nb].y, w1b.y, s[nb][4]);
                s[nb][6] = fmaf(xb[nb].z, w1b.z, s[nb][5]);
                s[nb][7] = fmaf(xb[nb].w, w1b.w, s[nb][6]);
                inc[nb] = s[nb][7];
            }

            // Batched warp scan over lane totals: 4 concurrent chains.
            #pragma unroll
            for (int o = 1; o < 32; o <<= 1) {
                const float v0 = __shfl_up_sync(FULL, inc[0], o);
                const float v1 = __shfl_up_sync(FULL, inc[1], o);
                const float v2 = __shfl_up_sync(FULL, inc[2], o);
                const float v3 = __shfl_up_sync(FULL, inc[3], o);
                if (lane >= o) {
                    inc[0] += v0; inc[1] += v1; inc[2] += v2; inc[3] += v3;
                }
            }
            float tot[4];
            #pragma unroll
            for (int nb = 0; nb < 4; nb++)
                tot[nb] = __shfl_sync(FULL, inc[nb], 31);

            #pragma unroll
            for (int nb = 0; nb < 4; nb++) {
                const float c2l = fmaf(0.5f, inc[nb] - s[nb][7], cb[h * 4 + nb]);
                float a[8];
                a[0] = c2l;
                #pragma unroll
                for (int m = 1; m < 8; m++)
                    a[m] = fmaf(0.5f, s[nb][m - 1], c2l);

                const float w2f[8] = {w2a.x, w2a.y, w2a.z, w2a.w,
                                      w2b.x, w2b.y, w2b.z, w2b.w};
                #pragma unroll
                for (int m = 0; m < 8; m++) {
                    const float tm = tanh_approx(a[m]);
                    acc[nb][m] = fmaf(fmaf(0.5f, tm, 0.5f), w2f[m], acc[nb][m]);
                }
                cb[h * 4 + nb] = fmaf(0.5f, tot[nb], cb[h * 4 + nb]);
            }
        }

        // Stage partials: warp w, batch nb, 256 l values (lane owns l=lane*8..+7).
        #pragma unroll
        for (int nb = 0; nb < 4; nb++) {
            float4* dst = reinterpret_cast<float4*>(&red[w][nb][lane * 8]);
            dst[0] = make_float4(acc[nb][0], acc[nb][1], acc[nb][2], acc[nb][3]);
            dst[1] = make_float4(acc[nb][4], acc[nb][5], acc[nb][6], acc[nb][7]);
        }
        __syncthreads();

        // 256 threads reduce 1024 outputs (4 each): nb = w>>1, half = w&1.
        {
            const int nbr = w >> 1;
            const int lb  = (w & 1) * 128 + lane;
            #pragma unroll
            for (int k = 0; k < 4; k++) {
                const int l = lb + k * 32;
                float sum = 0.f;
                #pragma unroll
                for (int ww = 0; ww < 8; ++ww) sum += red[ww][nbr][l];
                g_partial[g][b0 + nbr][q * 1024 + t * 256 + l] = sum;
            }
        }
        __syncthreads();
    }
}

// ---------------------------------------------------------------------------
// K2: combine 4 group partials + b2, accurate final sigmoid (float4/thread).
// ---------------------------------------------------------------------------
__global__ __launch_bounds__(256)
void nade_final_kernel(const float* __restrict__ b2,
                       float* __restrict__ out)
{
    const int idx4 = blockIdx.x * blockDim.x + threadIdx.x;  // 0..65535
    const int b = idx4 >> 10;
    const int r = idx4 & 1023;
    const float4 p0 = reinterpret_cast<const float4*>(&g_partial[0][b][0])[r];
    const float4 p1 = reinterpret_cast<const float4*>(&g_partial[1][b][0])[r];
    const float4 p2 = reinterpret_cast<const float4*>(&g_partial[2][b][0])[r];
    const float4 p3 = reinterpret_cast<const float4*>(&g_partial[3][b][0])[r];
    const float4 bv = reinterpret_cast<const float4*>(b2)[r];
    float4 o;
    o.x = 1.0f / (1.0f + __expf(-((p0.x + p1.x) + (p2.x + p3.x) + bv.x)));
    o.y = 1.0f / (1.0f + __expf(-((p0.y + p1.y) + (p2.y + p3.y) + bv.y)));
    o.z = 1.0f / (1.0f + __expf(-((p0.z + p1.z) + (p2.z + p3.z) + bv.z)));
    o.w = 1.0f / (1.0f + __expf(-((p0.w + p1.w) + (p2.w + p3.w) + bv.w)));
    reinterpret_cast<float4*>(out)[idx4] = o;
}

extern "C" void kernel_launch(void* const* d_in, const int* in_sizes, int n_in,
                              void* d_out, int out_size)
{
    const float* x  = (const float*)d_in[0];
    const float* W1 = (const float*)d_in[1];
    const float* b1 = (const float*)d_in[2];
    const float* W2 = (const float*)d_in[3];
    const float* b2 = (const float*)d_in[4];

    nade_carry_kernel<<<dim3(16, 8, 3), 256>>>(x, W1);
    nade_main_kernel<<<dim3(16, 4, 4), 256>>>(x, W1, b1, W2);
    nade_final_kernel<<<256, 256>>>(b2, (float*)d_out);
}

// round 10
// speedup vs baseline: 1.0500x; 1.0500x over previous
#include <cuda_runtime.h>

#define FULL 0xffffffffu

// Scratch (static device globals — allocation-free).
__device__ float g_partial[8][64][4096];   // per-(head-group,b,l) partials (8 MB)
__device__ float g_S[3][64][128];          // per-quarter dot partials S_q[b][i]

__device__ __forceinline__ float tanh_approx(float v) {
    float r;
    asm("tanh.approx.f32 %0, %1;" : "=f"(r) : "f"(v));
    return r;
}

// ---------------------------------------------------------------------------
// K0: quarter partial dots  S_q[b][i] = sum_{j in quarter q} W1[i,j]*x[b,j]
// grid (16 batch-quads, 16 head-chunks of 8, 3 quarters) = 768 blocks, 256 thr.
// NO smem, NO barrier. Warp owns 1 head x 4 batches; everything from L2
// (x rows are shared across the 16 head-chunk blocks -> L2 hits).
// Fully unrolled: ~40 outstanding LDG.128 per warp.
// ---------------------------------------------------------------------------
__global__ __launch_bounds__(256)
void nade_carry_kernel(const float* __restrict__ x,
                       const float* __restrict__ W1)
{
    const int bq   = blockIdx.x;               // batch quad
    const int hg   = blockIdx.y;               // head chunk (8 heads)
    const int q    = blockIdx.z;               // quarter 0..2
    const int w    = threadIdx.x >> 5;         // 8 warps
    const int lane = threadIdx.x & 31;

    const float4* x4   = reinterpret_cast<const float4*>(x);
    const float4* W1_4 = reinterpret_cast<const float4*>(W1);

    const int i = hg * 8 + w;                  // this warp's head

    float acc[4] = {0.f, 0.f, 0.f, 0.f};

    #pragma unroll
    for (int c = 0; c < 8; c++) {
        const int j4 = q * 256 + c * 32 + lane;    // float4 idx in row
        const float4 w1v = W1_4[i * 1024 + j4];
        #pragma unroll
        for (int nb = 0; nb < 4; nb++) {
            const float4 xv = x4[(bq * 4 + nb) * 1024 + j4];
            acc[nb] = fmaf(xv.x, w1v.x, fmaf(xv.y, w1v.y,
                      fmaf(xv.z, w1v.z, fmaf(xv.w, w1v.w, acc[nb]))));
        }
    }

    // Butterfly reduce the 4 accumulators (level-batched for overlap).
    #pragma unroll
    for (int o = 16; o > 0; o >>= 1) {
        #pragma unroll
        for (int nb = 0; nb < 4; nb++)
            acc[nb] += __shfl_down_sync(FULL, acc[nb], o);
    }
    if (lane == 0) {
        #pragma unroll
        for (int nb = 0; nb < 4; nb++)
            g_S[q][bq * 4 + nb][i] = acc[nb];
    }
}

// ---------------------------------------------------------------------------
// K1: scan + sigmoid + head reduction. 2 batches/block, 16 heads/block
// (warp = 2 heads x 2 batches), quarter of j.
// grid (32 bq, 8 head-groups, 4 quarters) = 1024 blocks, 256 thr.
// Low register state (~70) -> 3 blocks/SM (launch_bounds(256,3)), 6 warps/SMSP.
// The 4 chains (2h x 2nb) batch into ONE warp scan per tile.
// ---------------------------------------------------------------------------
__global__ __launch_bounds__(256, 3)
void nade_main_kernel(const float* __restrict__ x,
                      const float* __restrict__ W1,
                      const float* __restrict__ b1,
                      const float* __restrict__ W2)
{
    __shared__ float xs[2 * 1024];             // 8 KB: 2 batch quarter-rows
    __shared__ float red[8][2][128];           // 8 KB: warp partials

    const int b0   = blockIdx.x * 2;
    const int g    = blockIdx.y;               // head group of 16
    const int q    = blockIdx.z;
    const int tid  = threadIdx.x;
    const int w    = tid >> 5;                 // 8 warps, warp = 2 heads
    const int lane = tid & 31;

    const float4* x4  = reinterpret_cast<const float4*>(x);
    float4*       xs4 = reinterpret_cast<float4*>(xs);
    for (int idx = tid; idx < 512; idx += 256) {
        const int nb = idx >> 8;
        const int r  = idx & 255;
        xs4[idx] = x4[(b0 + nb) * 1024 + q * 256 + r];
    }
    __syncthreads();

    const int i0 = g * 16 + w * 2;

    // Chain c = h*2 + nb.  cb[c] = 0.5*(b1 + carry from previous quarters).
    float cb[4];
    #pragma unroll
    for (int h = 0; h < 2; h++) {
        const float base = b1[i0 + h];
        #pragma unroll
        for (int nb = 0; nb < 2; nb++) {
            float c = base;
            for (int qq = 0; qq < q; qq++) c += g_S[qq][b0 + nb][i0 + h];
            cb[h * 2 + nb] = 0.5f * c;
        }
    }

    const float4* W1_4 = reinterpret_cast<const float4*>(W1);
    const float4* W2_4 = reinterpret_cast<const float4*>(W2);

    for (int t = 0; t < 8; ++t) {
        const int jv = t * 32 + lane;          // float4 idx within quarter

        float4 xv[2];
        xv[0] = xs4[jv];
        xv[1] = xs4[256 + jv];

        float4 acc[2];
        acc[0] = make_float4(0.f, 0.f, 0.f, 0.f);
        acc[1] = make_float4(0.f, 0.f, 0.f, 0.f);

        float4 w1v[2], w2v[2];
        #pragma unroll
        for (int h = 0; h < 2; h++) {
            w1v[h] = W1_4[(i0 + h) * 1024 + q * 256 + jv];
            w2v[h] = W2_4[(i0 + h) * 1024 + q * 256 + jv];
        }

        // Per-lane inclusive partials for all 4 chains (h x nb).
        float s0[4], s1[4], s2[4], lt[4], inc[4];
        #pragma unroll
        for (int h = 0; h < 2; h++)
            #pragma unroll
            for (int nb = 0; nb < 2; nb++) {
                const int c = h * 2 + nb;
                s0[c] = xv[nb].x * w1v[h].x;
                s1[c] = fmaf(xv[nb].y, w1v[h].y, s0[c]);
                s2[c] = fmaf(xv[nb].z, w1v[h].z, s1[c]);
                lt[c] = fmaf(xv[nb].w, w1v[h].w, s2[c]);
                inc[c] = lt[c];
            }

        // ONE batched warp scan for all 4 chains.
        #pragma unroll
        for (int o = 1; o < 32; o <<= 1) {
            const float v0 = __shfl_up_sync(FULL, inc[0], o);
            const float v1 = __shfl_up_sync(FULL, inc[1], o);
            const float v2 = __shfl_up_sync(FULL, inc[2], o);
            const float v3 = __shfl_up_sync(FULL, inc[3], o);
            if (lane >= o) {
                inc[0] += v0; inc[1] += v1; inc[2] += v2; inc[3] += v3;
            }
        }
        float tot[4];
        #pragma unroll
        for (int c = 0; c < 4; c++)
            tot[c] = __shfl_sync(FULL, inc[c], 31);

        #pragma unroll
        for (int h = 0; h < 2; h++)
            #pragma unroll
            for (int nb = 0; nb < 2; nb++) {
                const int c = h * 2 + nb;
                const float c2l = fmaf(0.5f, inc[c] - lt[c], cb[c]);
                const float a0 = c2l;
                const float a1 = fmaf(0.5f, s0[c], c2l);
                const float a2 = fmaf(0.5f, s1[c], c2l);
                const float a3 = fmaf(0.5f, s2[c], c2l);

                const float t0 = tanh_approx(a0);
                const float t1 = tanh_approx(a1);
                const float t2 = tanh_approx(a2);
                const float t3 = tanh_approx(a3);

                acc[nb].x = fmaf(fmaf(0.5f, t0, 0.5f), w2v[h].x, acc[nb].x);
                acc[nb].y = fmaf(fmaf(0.5f, t1, 0.5f), w2v[h].y, acc[nb].y);
                acc[nb].z = fmaf(fmaf(0.5f, t2, 0.5f), w2v[h].z, acc[nb].z);
                acc[nb].w = fmaf(fmaf(0.5f, t3, 0.5f), w2v[h].w, acc[nb].w);

                cb[c] = fmaf(0.5f, tot[c], cb[c]);
            }

        // Stage partials: warp w, batch nb, 128 l values.
        reinterpret_cast<float4*>(&red[w][0][0])[lane] = acc[0];
        reinterpret_cast<float4*>(&red[w][1][0])[lane] = acc[1];
        __syncthreads();

        // 256 threads reduce 256 outputs: nb = tid>>7, l = tid&127.
        {
            const int nbr = tid >> 7;
            const int l   = tid & 127;
            float sum = 0.f;
            #pragma unroll
            for (int ww = 0; ww < 8; ++ww) sum += red[ww][nbr][l];
            g_partial[g][b0 + nbr][q * 1024 + t * 128 + l] = sum;
        }
        __syncthreads();
    }
}

// ---------------------------------------------------------------------------
// K2: combine 8 group partials + b2, accurate final sigmoid (float4/thread).
// ---------------------------------------------------------------------------
__global__ __launch_bounds__(256)
void nade_final_kernel(const float* __restrict__ b2,
                       float* __restrict__ out)
{
    const int idx4 = blockIdx.x * blockDim.x + threadIdx.x;  // 0..65535
    const int b = idx4 >> 10;
    const int r = idx4 & 1023;

    float4 s = reinterpret_cast<const float4*>(b2)[r];
    #pragma unroll
    for (int g = 0; g < 8; g++) {
        const float4 p = reinterpret_cast<const float4*>(&g_partial[g][b][0])[r];
        s.x += p.x; s.y += p.y; s.z += p.z; s.w += p.w;
    }
    float4 o;
    o.x = 1.0f / (1.0f + __expf(-s.x));
    o.y = 1.0f / (1.0f + __expf(-s.y));
    o.z = 1.0f / (1.0f + __expf(-s.z));
    o.w = 1.0f / (1.0f + __expf(-s.w));
    reinterpret_cast<float4*>(out)[idx4] = o;
}

extern "C" void kernel_launch(void* const* d_in, const int* in_sizes, int n_in,
                              void* d_out, int out_size)
{
    const float* x  = (const float*)d_in[0];
    const float* W1 = (const float*)d_in[1];
    const float* b1 = (const float*)d_in[2];
    const float* W2 = (const float*)d_in[3];
    const float* b2 = (const float*)d_in[4];

    nade_carry_kernel<<<dim3(16, 16, 3), 256>>>(x, W1);
    nade_main_kernel<<<dim3(32, 8, 4), 256>>>(x, W1, b1, W2);
    nade_final_kernel<<<256, 256>>>(b2, (float*)d_out);
}